// round 3
// baseline (speedup 1.0000x reference)
#include <cuda_runtime.h>
#include <cstdint>
#include <cstddef>

// ---------------------------------------------------------------------------
// MPConv fused GNN edge-MLP + scatter on GB300 (sm_103a)
// R3: packed fma.rn.f32x2 (FFMA2) GEMMs, 8ch x 8edge microtile, E_TILE=256,
//     pre-duplicated weight pairs in smem (zero per-iter packing).
// ---------------------------------------------------------------------------

#define NODES_MAX 100000
#define E_TILE    256
#define NTHREADS  256

typedef unsigned long long ull_t;

__device__ __align__(16) float g_AB[(size_t)NODES_MAX * 128];
__device__ int g_idx64;

__device__ __forceinline__ float gelu_exact(float v) {
    return 0.5f * v * (1.0f + erff(v * 0.70710678118654752440f));
}

__device__ __forceinline__ void fma2(ull_t& d, ull_t a, ull_t b) {
    asm("fma.rn.f32x2 %0, %1, %2, %0;" : "+l"(d) : "l"(a), "l"(b));
}
#define UNPK(lo, hi, v) asm("mov.b64 {%0,%1}, %2;" : "=f"(lo), "=f"(hi) : "l"(v))

// ---------------------------------------------------------------------------
__global__ void zero_kernel(float4* out, int n4) {
    int idx = blockIdx.x * blockDim.x + threadIdx.x;
    if (idx < n4) out[idx] = make_float4(0.f, 0.f, 0.f, 0.f);
}

__global__ void detect_idx_kernel(const void* edge_index, int N) {
    const long long* p64 = (const long long*)edge_index;
    int ok64 = 1;
    for (int e = 0; e < 128; ++e) {
        long long v = p64[e];
        if (v < 0 || v >= (long long)N) { ok64 = 0; break; }
    }
    g_idx64 = ok64;
}

__device__ __forceinline__ int load_edge_idx(const void* ei, long long pos, int idx64) {
    if (idx64) return (int)((const long long*)ei)[pos];
    return ((const int*)ei)[pos];
}

// ---------------------------------------------------------------------------
// Precompute g_AB (unchanged from R2: ~45us, not on critical path yet)
#define FMA_ROW(ACC, A, B)                          \
    ACC.x = fmaf((A), (B).x, ACC.x);                \
    ACC.y = fmaf((A), (B).y, ACC.y);                \
    ACC.z = fmaf((A), (B).z, ACC.z);                \
    ACC.w = fmaf((A), (B).w, ACC.w);

__global__ void __launch_bounds__(NTHREADS, 2)
precompute_kernel(const float* __restrict__ x,
                  const float* __restrict__ W1,
                  const float* __restrict__ b1,
                  int N) {
    extern __shared__ float sm[];
    float* xT = sm;              // [k][node] 64x64
    float* Wc = sm + 64 * 64;    // [k][c]    64x128

    int t = threadIdx.x;
    int n_base = blockIdx.x * 64;

#pragma unroll
    for (int it = 0; it < 32; ++it) {
        int idx = t + it * NTHREADS;
        int k = idx >> 7, c = idx & 127;
        Wc[idx] = (c < 64) ? W1[k * 64 + c] : W1[(64 + k) * 64 + (c - 64)];
    }
#pragma unroll
    for (int it = 0; it < 16; ++it) {
        int idx = t + it * NTHREADS;
        int node = idx >> 6, k = idx & 63;
        int gn = n_base + node;
        xT[k * 64 + node] = (gn < N) ? x[(size_t)gn * 64 + k] : 0.f;
    }
    __syncthreads();

    int tx = t & 31, ty = t >> 5;
    int c0 = tx * 4, n0 = ty * 8;

    float4 acc[8];
#pragma unroll
    for (int r = 0; r < 8; ++r) acc[r] = make_float4(0.f, 0.f, 0.f, 0.f);

#pragma unroll 8
    for (int k = 0; k < 64; ++k) {
        float4 b  = *(const float4*)&Wc[k * 128 + c0];
        float4 a0 = *(const float4*)&xT[k * 64 + n0];
        float4 a1 = *(const float4*)&xT[k * 64 + n0 + 4];
        FMA_ROW(acc[0], a0.x, b); FMA_ROW(acc[1], a0.y, b);
        FMA_ROW(acc[2], a0.z, b); FMA_ROW(acc[3], a0.w, b);
        FMA_ROW(acc[4], a1.x, b); FMA_ROW(acc[5], a1.y, b);
        FMA_ROW(acc[6], a1.z, b); FMA_ROW(acc[7], a1.w, b);
    }

    float4 badd = make_float4(0.f, 0.f, 0.f, 0.f);
    if (c0 < 64) badd = *(const float4*)&b1[c0];

#pragma unroll
    for (int r = 0; r < 8; ++r) {
        int gn = n_base + n0 + r;
        if (gn < N) {
            float4 v = acc[r];
            v.x += badd.x; v.y += badd.y; v.z += badd.z; v.w += badd.w;
            *(float4*)&g_AB[(size_t)gn * 128 + c0] = v;
        }
    }
}

// ---------------------------------------------------------------------------
// Main edge kernel. 256 edges/block, 256 threads, 8ch x 8edge per thread.
// dyn smem (bytes):
//   iidx[256] @0, jidx[256] @1024                  (2 KB)
//   eaT [32][264] f32  @2048      (33792)
//   hT  [64][264] f32  @35840     (67584)
//   W1d [32][64]  ull  @103424    (16384)   duplicated pairs (w,w)
//   W2d [64][64]  ull  @119808    (32768)
//   total 152576
__global__ void __launch_bounds__(NTHREADS, 1)
mpconv_kernel(const void* __restrict__ edge_index,
              const float* __restrict__ edge_attr,
              const float* __restrict__ W1,
              const float* __restrict__ gamma,
              const float* __restrict__ beta,
              const float* __restrict__ W2,
              const float* __restrict__ b2,
              float* __restrict__ out,
              int E) {
    extern __shared__ char smraw[];
    int*   iidx = (int*)smraw;
    int*   jidx = iidx + 256;
    float* eaT  = (float*)(smraw + 2048);
    float* hT   = (float*)(smraw + 35840);
    ull_t* W1d  = (ull_t*)(smraw + 103424);
    ull_t* W2d  = (ull_t*)(smraw + 119808);

    int t = threadIdx.x;
    long long e_base = (long long)blockIdx.x * E_TILE;
    int idx64 = g_idx64;

    // edge indices (E multiple of 256)
    iidx[t] = load_edge_idx(edge_index, e_base + t, idx64);
    jidx[t] = load_edge_idx(edge_index, (long long)E + e_base + t, idx64);

    // duplicated weight pairs: W1 rows 128..159 (2048 pairs) + W2 (4096 pairs)
#pragma unroll
    for (int it = 0; it < 24; ++it) {
        int slot = t + it * NTHREADS;               // 0..6143
        float v;
        float2* dst;
        if (slot < 2048) { v = W1[128 * 64 + slot]; dst = (float2*)W1d + slot; }
        else             { v = W2[slot - 2048];     dst = (float2*)W2d + (slot - 2048); }
        *dst = make_float2(v, v);
    }

    // edge_attr transposed: eaT[k][e]
    {
        const float4* ea4 = (const float4*)edge_attr;
#pragma unroll
        for (int it = 0; it < 8; ++it) {
            int slot = t + it * NTHREADS;           // 0..2047
            int e = slot >> 3, q = slot & 7;
            float4 v = ea4[e_base * 8 + slot];
            int k = q * 4;
            eaT[(k + 0) * 264 + e] = v.x;
            eaT[(k + 1) * 264 + e] = v.y;
            eaT[(k + 2) * 264 + e] = v.z;
            eaT[(k + 3) * 264 + e] = v.w;
        }
    }
    __syncthreads();

    int tx = t & 7, ty = t >> 3;
    int c0 = tx * 8, e0 = ty * 8;

    ull_t acc[32];            // acc[c*4+ep] : channel c (0..7), edge-pair ep (0..3)
#pragma unroll
    for (int i = 0; i < 32; ++i) acc[i] = 0ull;

#define GEMM_STEP(WD, ABASE, KK)                                               \
    {                                                                          \
        const ull_t* bp = &(WD)[(KK) * 64 + c0];                               \
        ulonglong2 b01 = *(const ulonglong2*)(bp + 0);                         \
        ulonglong2 b23 = *(const ulonglong2*)(bp + 2);                         \
        ulonglong2 b45 = *(const ulonglong2*)(bp + 4);                         \
        ulonglong2 b67 = *(const ulonglong2*)(bp + 6);                         \
        const float* ap = (ABASE) + (KK) * 264 + e0;                           \
        ulonglong2 A01 = *(const ulonglong2*)(ap);                             \
        ulonglong2 A23 = *(const ulonglong2*)(ap + 4);                         \
        fma2(acc[ 0], A01.x, b01.x); fma2(acc[ 1], A01.y, b01.x);              \
        fma2(acc[ 2], A23.x, b01.x); fma2(acc[ 3], A23.y, b01.x);              \
        fma2(acc[ 4], A01.x, b01.y); fma2(acc[ 5], A01.y, b01.y);              \
        fma2(acc[ 6], A23.x, b01.y); fma2(acc[ 7], A23.y, b01.y);              \
        fma2(acc[ 8], A01.x, b23.x); fma2(acc[ 9], A01.y, b23.x);              \
        fma2(acc[10], A23.x, b23.x); fma2(acc[11], A23.y, b23.x);              \
        fma2(acc[12], A01.x, b23.y); fma2(acc[13], A01.y, b23.y);              \
        fma2(acc[14], A23.x, b23.y); fma2(acc[15], A23.y, b23.y);              \
        fma2(acc[16], A01.x, b45.x); fma2(acc[17], A01.y, b45.x);              \
        fma2(acc[18], A23.x, b45.x); fma2(acc[19], A23.y, b45.x);              \
        fma2(acc[20], A01.x, b45.y); fma2(acc[21], A01.y, b45.y);              \
        fma2(acc[22], A23.x, b45.y); fma2(acc[23], A23.y, b45.y);              \
        fma2(acc[24], A01.x, b67.x); fma2(acc[25], A01.y, b67.x);              \
        fma2(acc[26], A23.x, b67.x); fma2(acc[27], A23.y, b67.x);              \
        fma2(acc[28], A01.x, b67.y); fma2(acc[29], A01.y, b67.y);              \
        fma2(acc[30], A23.x, b67.y); fma2(acc[31], A23.y, b67.y);              \
    }

    // -------- GEMM1: h = ea @ W1c --------
#pragma unroll 4
    for (int kk = 0; kk < 32; ++kk) GEMM_STEP(W1d, eaT, kk)

    // unpack to hv[c][e]
    float hv[8][8];
#pragma unroll
    for (int c = 0; c < 8; ++c) {
        UNPK(hv[c][0], hv[c][1], acc[c * 4 + 0]);
        UNPK(hv[c][2], hv[c][3], acc[c * 4 + 1]);
        UNPK(hv[c][4], hv[c][5], acc[c * 4 + 2]);
        UNPK(hv[c][6], hv[c][7], acc[c * 4 + 3]);
    }

    // -------- gather precomputed node parts --------
    const float4* AB4 = (const float4*)g_AB;
#pragma unroll
    for (int r = 0; r < 8; ++r) {
        int e = e0 + r;
        int vi = iidx[e], vj = jidx[e];
        float4 a0 = AB4[(size_t)vi * 32 + tx * 2];
        float4 a1 = AB4[(size_t)vi * 32 + tx * 2 + 1];
        float4 q0 = AB4[(size_t)vj * 32 + 16 + tx * 2];
        float4 q1 = AB4[(size_t)vj * 32 + 16 + tx * 2 + 1];
        hv[0][r] += a0.x + q0.x; hv[1][r] += a0.y + q0.y;
        hv[2][r] += a0.z + q0.z; hv[3][r] += a0.w + q0.w;
        hv[4][r] += a1.x + q1.x; hv[5][r] += a1.y + q1.y;
        hv[6][r] += a1.z + q1.z; hv[7][r] += a1.w + q1.w;
    }

    // -------- LayerNorm + GELU --------
    float4 gA = *(const float4*)&gamma[c0];
    float4 gB = *(const float4*)&gamma[c0 + 4];
    float4 bA = *(const float4*)&beta[c0];
    float4 bB = *(const float4*)&beta[c0 + 4];
    float gm[8] = {gA.x, gA.y, gA.z, gA.w, gB.x, gB.y, gB.z, gB.w};
    float bt[8] = {bA.x, bA.y, bA.z, bA.w, bB.x, bB.y, bB.z, bB.w};

#pragma unroll
    for (int r = 0; r < 8; ++r) {
        float s = 0.f, s2 = 0.f;
#pragma unroll
        for (int c = 0; c < 8; ++c) {
            s += hv[c][r];
            s2 = fmaf(hv[c][r], hv[c][r], s2);
        }
        // reduce across the 8 tx lanes holding this edge's 64 channels
#pragma unroll
        for (int off = 4; off >= 1; off >>= 1) {
            s  += __shfl_xor_sync(0xffffffffu, s,  off, 8);
            s2 += __shfl_xor_sync(0xffffffffu, s2, off, 8);
        }
        float mu   = s * (1.0f / 64.0f);
        float var  = s2 * (1.0f / 64.0f) - mu * mu;
        float rstd = rsqrtf(var + 1e-5f);
#pragma unroll
        for (int c = 0; c < 8; ++c)
            hv[c][r] = gelu_exact((hv[c][r] - mu) * rstd * gm[c] + bt[c]);
    }

    // store hT[c][e] (transposed activations for GEMM2)
#pragma unroll
    for (int c = 0; c < 8; ++c) {
        *(float4*)&hT[(c0 + c) * 264 + e0] =
            make_float4(hv[c][0], hv[c][1], hv[c][2], hv[c][3]);
        *(float4*)&hT[(c0 + c) * 264 + e0 + 4] =
            make_float4(hv[c][4], hv[c][5], hv[c][6], hv[c][7]);
    }
    __syncthreads();

    // -------- GEMM2: m = g @ W2 --------
#pragma unroll
    for (int i = 0; i < 32; ++i) acc[i] = 0ull;
#pragma unroll 4
    for (int kk = 0; kk < 64; ++kk) GEMM_STEP(W2d, hT, kk)

    float mv[8][8];
#pragma unroll
    for (int c = 0; c < 8; ++c) {
        UNPK(mv[c][0], mv[c][1], acc[c * 4 + 0]);
        UNPK(mv[c][2], mv[c][3], acc[c * 4 + 1]);
        UNPK(mv[c][4], mv[c][5], acc[c * 4 + 2]);
        UNPK(mv[c][6], mv[c][7], acc[c * 4 + 3]);
    }

    // -------- scatter-add onto out[j] --------
    float4 b2A = *(const float4*)&b2[c0];
    float4 b2B = *(const float4*)&b2[c0 + 4];
#pragma unroll
    for (int r = 0; r < 8; ++r) {
        int e = e0 + r;
        int vj = jidx[e];
        float* p = out + (size_t)vj * 64 + c0;
        float x0 = mv[0][r] + b2A.x, x1 = mv[1][r] + b2A.y;
        float x2 = mv[2][r] + b2A.z, x3 = mv[3][r] + b2A.w;
        float x4 = mv[4][r] + b2B.x, x5 = mv[5][r] + b2B.y;
        float x6 = mv[6][r] + b2B.z, x7 = mv[7][r] + b2B.w;
        asm volatile("red.global.add.v4.f32 [%0], {%1,%2,%3,%4};"
                     :: "l"(p), "f"(x0), "f"(x1), "f"(x2), "f"(x3) : "memory");
        asm volatile("red.global.add.v4.f32 [%0], {%1,%2,%3,%4};"
                     :: "l"(p + 4), "f"(x4), "f"(x5), "f"(x6), "f"(x7) : "memory");
    }
}

// ---------------------------------------------------------------------------
extern "C" void kernel_launch(void* const* d_in, const int* in_sizes, int n_in,
                              void* d_out, int out_size) {
    const float* x          = (const float*)d_in[0];
    const void*  edge_index = d_in[1];
    const float* edge_attr  = (const float*)d_in[2];
    const float* W1         = (const float*)d_in[3];
    const float* b1         = (const float*)d_in[4];
    const float* gamma      = (const float*)d_in[5];
    const float* beta       = (const float*)d_in[6];
    const float* W2         = (const float*)d_in[7];
    const float* b2         = (const float*)d_in[8];
    float*       out        = (float*)d_out;

    int N = in_sizes[0] / 64;     // 100000
    int E = in_sizes[2] / 32;     // 1600000

    const int SM_PRE  = (64 * 64 + 64 * 128) * 4;   // 49152
    const int SM_MAIN = 152576;
    cudaFuncSetAttribute(precompute_kernel, cudaFuncAttributeMaxDynamicSharedMemorySize, SM_PRE);
    cudaFuncSetAttribute(mpconv_kernel,     cudaFuncAttributeMaxDynamicSharedMemorySize, SM_MAIN);

    int n4 = out_size / 4;
    detect_idx_kernel<<<1, 1>>>(edge_index, N);
    zero_kernel<<<(n4 + 255) / 256, 256>>>((float4*)out, n4);
    precompute_kernel<<<(N + 63) / 64, NTHREADS, SM_PRE>>>(x, W1, b1, N);
    mpconv_kernel<<<E / E_TILE, NTHREADS, SM_MAIN>>>(edge_index, edge_attr, W1,
                                                     gamma, beta, W2, b2, out, E);
}

// round 4
// speedup vs baseline: 1.9496x; 1.9496x over previous
#include <cuda_runtime.h>
#include <cstdint>
#include <cstddef>

// ---------------------------------------------------------------------------
// MPConv fused GNN edge-MLP + scatter on GB300 (sm_103a)
// R4 = R2 skeleton (proved 564us) + fma.rn.f32x2 inner loops +
//      conflict-free permuted duplicated-weight smem layout + 2 CTAs/SM.
// ---------------------------------------------------------------------------

#define NODES_MAX 100000
#define E_TILE    128
#define NTHREADS  256

typedef unsigned long long ull_t;

__device__ __align__(16) float g_AB[(size_t)NODES_MAX * 128];
__device__ int g_idx64;

__device__ __forceinline__ float gelu_exact(float v) {
    return 0.5f * v * (1.0f + erff(v * 0.70710678118654752440f));
}

__device__ __forceinline__ void fma2(ull_t& d, ull_t a, ull_t b) {
    asm("fma.rn.f32x2 %0, %1, %2, %0;" : "+l"(d) : "l"(a), "l"(b));
}
#define UNPK(lo, hi, v) asm("mov.b64 {%0,%1}, %2;" : "=f"(lo), "=f"(hi) : "l"(v))

// storage permutation for duplicated weight pairs (8B slots), 64 slots/row:
// channel c -> slot ((c>>1)&1)*32 + (c>>2)*2 + (c&1)
// thread tx (0..15) then reads its 4 channels c0=tx*4 as TWO 16B loads at
// byte offsets  tx*16  and  256 + tx*16  -> consecutive tx 4 banks apart,
// all 32 banks covered per phase: conflict-free.
__device__ __forceinline__ int wperm(int c) {
    return ((c >> 1) & 1) * 32 + (c >> 2) * 2 + (c & 1);
}

// ---------------------------------------------------------------------------
__global__ void zero_kernel(float4* out, int n4) {
    int idx = blockIdx.x * blockDim.x + threadIdx.x;
    if (idx < n4) out[idx] = make_float4(0.f, 0.f, 0.f, 0.f);
}

__global__ void detect_idx_kernel(const void* edge_index, int N) {
    const long long* p64 = (const long long*)edge_index;
    int ok64 = 1;
    for (int e = 0; e < 128; ++e) {
        long long v = p64[e];
        if (v < 0 || v >= (long long)N) { ok64 = 0; break; }
    }
    g_idx64 = ok64;
}

__device__ __forceinline__ int load_edge_idx(const void* ei, long long pos, int idx64) {
    if (idx64) return (int)((const long long*)ei)[pos];
    return ((const int*)ei)[pos];
}

// ---------------------------------------------------------------------------
#define FMA_ROW(ACC, A, B)                          \
    ACC.x = fmaf((A), (B).x, ACC.x);                \
    ACC.y = fmaf((A), (B).y, ACC.y);                \
    ACC.z = fmaf((A), (B).z, ACC.z);                \
    ACC.w = fmaf((A), (B).w, ACC.w);

__global__ void __launch_bounds__(NTHREADS, 2)
precompute_kernel(const float* __restrict__ x,
                  const float* __restrict__ W1,
                  const float* __restrict__ b1,
                  int N) {
    extern __shared__ float sm[];
    float* xT = sm;              // [k][node] 64x64
    float* Wc = sm + 64 * 64;    // [k][c]    64x128

    int t = threadIdx.x;
    int n_base = blockIdx.x * 64;

#pragma unroll
    for (int it = 0; it < 32; ++it) {
        int idx = t + it * NTHREADS;
        int k = idx >> 7, c = idx & 127;
        Wc[idx] = (c < 64) ? W1[k * 64 + c] : W1[(64 + k) * 64 + (c - 64)];
    }
#pragma unroll
    for (int it = 0; it < 16; ++it) {
        int idx = t + it * NTHREADS;
        int node = idx >> 6, k = idx & 63;
        int gn = n_base + node;
        xT[k * 64 + node] = (gn < N) ? x[(size_t)gn * 64 + k] : 0.f;
    }
    __syncthreads();

    int tx = t & 31, ty = t >> 5;
    int c0 = tx * 4, n0 = ty * 8;

    float4 acc[8];
#pragma unroll
    for (int r = 0; r < 8; ++r) acc[r] = make_float4(0.f, 0.f, 0.f, 0.f);

#pragma unroll 8
    for (int k = 0; k < 64; ++k) {
        float4 b  = *(const float4*)&Wc[k * 128 + c0];
        float4 a0 = *(const float4*)&xT[k * 64 + n0];
        float4 a1 = *(const float4*)&xT[k * 64 + n0 + 4];
        FMA_ROW(acc[0], a0.x, b); FMA_ROW(acc[1], a0.y, b);
        FMA_ROW(acc[2], a0.z, b); FMA_ROW(acc[3], a0.w, b);
        FMA_ROW(acc[4], a1.x, b); FMA_ROW(acc[5], a1.y, b);
        FMA_ROW(acc[6], a1.z, b); FMA_ROW(acc[7], a1.w, b);
    }

    float4 badd = make_float4(0.f, 0.f, 0.f, 0.f);
    if (c0 < 64) badd = *(const float4*)&b1[c0];

#pragma unroll
    for (int r = 0; r < 8; ++r) {
        int gn = n_base + n0 + r;
        if (gn < N) {
            float4 v = acc[r];
            v.x += badd.x; v.y += badd.y; v.z += badd.z; v.w += badd.w;
            *(float4*)&g_AB[(size_t)gn * 128 + c0] = v;
        }
    }
}

// ---------------------------------------------------------------------------
// Main edge kernel. 128 edges/block, 256 threads, 4ch x 8edge per thread.
// dyn smem (bytes):
//   iidx[128] @0, jidx[128] @512
//   W1d [32][64] ull @1024   (16384)   permuted duplicated pairs
//   W2d [64][64] ull @17408  (32768)
//   eaT [32][132] f32 @50176 (16896)
//   hT  [64][132] f32 @67072 (33792)
//   total 100864  -> 2 CTAs/SM
__global__ void __launch_bounds__(NTHREADS, 2)
mpconv_kernel(const void* __restrict__ edge_index,
              const float* __restrict__ edge_attr,
              const float* __restrict__ W1,
              const float* __restrict__ gamma,
              const float* __restrict__ beta,
              const float* __restrict__ W2,
              const float* __restrict__ b2,
              float* __restrict__ out,
              int E) {
    extern __shared__ char smraw[];
    int*   iidx = (int*)smraw;
    int*   jidx = iidx + 128;
    ull_t* W1d  = (ull_t*)(smraw + 1024);
    ull_t* W2d  = (ull_t*)(smraw + 17408);
    float* eaT  = (float*)(smraw + 50176);
    float* hT   = (float*)(smraw + 67072);

    int t = threadIdx.x;
    long long e_base = (long long)blockIdx.x * E_TILE;
    int idx64 = g_idx64;

    // edge indices (E multiple of 128)
    if (t < 128) iidx[t] = load_edge_idx(edge_index, e_base + t, idx64);
    else         jidx[t - 128] = load_edge_idx(edge_index, (long long)E + e_base + (t - 128), idx64);

    // duplicated + permuted weight pairs
#pragma unroll
    for (int it = 0; it < 24; ++it) {
        int slot = t + it * NTHREADS;               // 0..6143
        float v;
        float2* dst;
        if (slot < 2048) {
            int k = slot >> 6, c = slot & 63;
            v = W1[128 * 64 + slot];
            dst = (float2*)W1d + k * 64 + wperm(c);
        } else {
            int s = slot - 2048;
            int k = s >> 6, c = s & 63;
            v = W2[s];
            dst = (float2*)W2d + k * 64 + wperm(c);
        }
        *dst = make_float2(v, v);
    }

    // edge_attr transposed: eaT[k][e]
    {
        const float4* ea4 = (const float4*)edge_attr;
#pragma unroll
        for (int it = 0; it < 4; ++it) {
            int slot = t + it * NTHREADS;           // 0..1023
            int e = slot >> 3, q = slot & 7;
            float4 v = ea4[e_base * 8 + slot];
            int k = q * 4;
            eaT[(k + 0) * 132 + e] = v.x;
            eaT[(k + 1) * 132 + e] = v.y;
            eaT[(k + 2) * 132 + e] = v.z;
            eaT[(k + 3) * 132 + e] = v.w;
        }
    }
    __syncthreads();

    int tx = t & 15, ty = t >> 4;
    int c0 = tx * 4, e0 = ty * 8;

    // acc[c*4+p]: channel c (0..3), edge-pair p (0..3)
    ull_t acc[16];
#pragma unroll
    for (int i = 0; i < 16; ++i) acc[i] = 0ull;

#define GEMM_STEP(WD, ABASE, KK)                                               \
    {                                                                          \
        const ull_t* wp = (WD) + (KK) * 64 + tx * 2;                           \
        ulonglong2 b0 = *(const ulonglong2*)(wp);        /* ch c0, c0+1 */     \
        ulonglong2 b1 = *(const ulonglong2*)(wp + 32);   /* ch c0+2, c0+3 */   \
        const float* ap = (ABASE) + (KK) * 132 + e0;                           \
        ulonglong2 A01 = *(const ulonglong2*)(ap);                             \
        ulonglong2 A23 = *(const ulonglong2*)(ap + 4);                         \
        fma2(acc[ 0], A01.x, b0.x); fma2(acc[ 1], A01.y, b0.x);                \
        fma2(acc[ 2], A23.x, b0.x); fma2(acc[ 3], A23.y, b0.x);                \
        fma2(acc[ 4], A01.x, b0.y); fma2(acc[ 5], A01.y, b0.y);                \
        fma2(acc[ 6], A23.x, b0.y); fma2(acc[ 7], A23.y, b0.y);                \
        fma2(acc[ 8], A01.x, b1.x); fma2(acc[ 9], A01.y, b1.x);                \
        fma2(acc[10], A23.x, b1.x); fma2(acc[11], A23.y, b1.x);                \
        fma2(acc[12], A01.x, b1.y); fma2(acc[13], A01.y, b1.y);                \
        fma2(acc[14], A23.x, b1.y); fma2(acc[15], A23.y, b1.y);                \
    }

    // -------- GEMM1: h = ea @ W1c --------
#pragma unroll 4
    for (int kk = 0; kk < 32; ++kk) GEMM_STEP(W1d, eaT, kk)

    float hv[4][8];
#pragma unroll
    for (int c = 0; c < 4; ++c) {
#pragma unroll
        for (int p = 0; p < 4; ++p)
            UNPK(hv[c][2 * p], hv[c][2 * p + 1], acc[c * 4 + p]);
    }

    // -------- gather precomputed node parts --------
    const float4* AB4 = (const float4*)g_AB;
#pragma unroll
    for (int r = 0; r < 8; ++r) {
        int e = e0 + r;
        int vi = iidx[e], vj = jidx[e];
        float4 av = AB4[(size_t)vi * 32 + tx];        // A part
        float4 bv = AB4[(size_t)vj * 32 + 16 + tx];   // B part
        hv[0][r] += av.x + bv.x;
        hv[1][r] += av.y + bv.y;
        hv[2][r] += av.z + bv.z;
        hv[3][r] += av.w + bv.w;
    }

    // -------- LayerNorm + GELU --------
    float4 gmv = *(const float4*)&gamma[c0];
    float4 btv = *(const float4*)&beta[c0];
    float gm[4] = {gmv.x, gmv.y, gmv.z, gmv.w};
    float bt[4] = {btv.x, btv.y, btv.z, btv.w};

#pragma unroll
    for (int r = 0; r < 8; ++r) {
        float s = 0.f, s2 = 0.f;
#pragma unroll
        for (int c = 0; c < 4; ++c) {
            s += hv[c][r];
            s2 = fmaf(hv[c][r], hv[c][r], s2);
        }
#pragma unroll
        for (int off = 8; off >= 1; off >>= 1) {
            s  += __shfl_xor_sync(0xffffffffu, s,  off, 16);
            s2 += __shfl_xor_sync(0xffffffffu, s2, off, 16);
        }
        float mu   = s * (1.0f / 64.0f);
        float var  = s2 * (1.0f / 64.0f) - mu * mu;
        float rstd = rsqrtf(var + 1e-5f);
#pragma unroll
        for (int c = 0; c < 4; ++c)
            hv[c][r] = gelu_exact((hv[c][r] - mu) * rstd * gm[c] + bt[c]);
    }

    // store transposed activations hT[c][e]
#pragma unroll
    for (int c = 0; c < 4; ++c) {
        *(float4*)&hT[(c0 + c) * 132 + e0] =
            make_float4(hv[c][0], hv[c][1], hv[c][2], hv[c][3]);
        *(float4*)&hT[(c0 + c) * 132 + e0 + 4] =
            make_float4(hv[c][4], hv[c][5], hv[c][6], hv[c][7]);
    }
    __syncthreads();

    // -------- GEMM2: m = g @ W2 --------
#pragma unroll
    for (int i = 0; i < 16; ++i) acc[i] = 0ull;
#pragma unroll 4
    for (int kk = 0; kk < 64; ++kk) GEMM_STEP(W2d, hT, kk)

    float mv[4][8];
#pragma unroll
    for (int c = 0; c < 4; ++c) {
#pragma unroll
        for (int p = 0; p < 4; ++p)
            UNPK(mv[c][2 * p], mv[c][2 * p + 1], acc[c * 4 + p]);
    }

    // -------- scatter-add onto out[j] --------
    float4 b2v = *(const float4*)&b2[c0];
#pragma unroll
    for (int r = 0; r < 8; ++r) {
        int e = e0 + r;
        int vj = jidx[e];
        float* p = out + (size_t)vj * 64 + c0;
        float x0 = mv[0][r] + b2v.x, x1 = mv[1][r] + b2v.y;
        float x2 = mv[2][r] + b2v.z, x3 = mv[3][r] + b2v.w;
        asm volatile("red.global.add.v4.f32 [%0], {%1,%2,%3,%4};"
                     :: "l"(p), "f"(x0), "f"(x1), "f"(x2), "f"(x3) : "memory");
    }
}

// ---------------------------------------------------------------------------
extern "C" void kernel_launch(void* const* d_in, const int* in_sizes, int n_in,
                              void* d_out, int out_size) {
    const float* x          = (const float*)d_in[0];
    const void*  edge_index = d_in[1];
    const float* edge_attr  = (const float*)d_in[2];
    const float* W1         = (const float*)d_in[3];
    const float* b1         = (const float*)d_in[4];
    const float* gamma      = (const float*)d_in[5];
    const float* beta       = (const float*)d_in[6];
    const float* W2         = (const float*)d_in[7];
    const float* b2         = (const float*)d_in[8];
    float*       out        = (float*)d_out;

    int N = in_sizes[0] / 64;     // 100000
    int E = in_sizes[2] / 32;     // 1600000

    const int SM_PRE  = (64 * 64 + 64 * 128) * 4;   // 49152
    const int SM_MAIN = 100864;
    cudaFuncSetAttribute(precompute_kernel, cudaFuncAttributeMaxDynamicSharedMemorySize, SM_PRE);
    cudaFuncSetAttribute(mpconv_kernel,     cudaFuncAttributeMaxDynamicSharedMemorySize, SM_MAIN);

    int n4 = out_size / 4;
    detect_idx_kernel<<<1, 1>>>(edge_index, N);
    zero_kernel<<<(n4 + 255) / 256, 256>>>((float4*)out, n4);
    precompute_kernel<<<(N + 63) / 64, NTHREADS, SM_PRE>>>(x, W1, b1, N);
    mpconv_kernel<<<E / E_TILE, NTHREADS, SM_MAIN>>>(edge_index, edge_attr, W1,
                                                     gamma, beta, W2, b2, out, E);
}

// round 5
// speedup vs baseline: 3.7002x; 1.8980x over previous
#include <cuda_runtime.h>
#include <cstdint>
#include <cstddef>

// ---------------------------------------------------------------------------
// MPConv fused GNN edge-MLP + scatter on GB300 (sm_103a)
// R5: GEMM2 hoisted to node side via linearity of segment_sum:
//   A = x @ W1[0:64] + b1 ; B = x @ W1[64:128]          (per node)
//   edge e: h = A[i] + B[j] + ea @ W1c
//           g = gelu(LN(h));  G[j] += g ; deg[j] += 1   (atomic scatter)
//   node n: out[n] = G[n] @ W2 + deg[n] * b2
// ---------------------------------------------------------------------------

#define NODES_MAX 100000
#define E_TILE    128
#define NTHREADS  256

typedef unsigned long long ull_t;

__device__ __align__(16) float g_AB[(size_t)NODES_MAX * 128];   // A||B per node
__device__ __align__(16) float g_G[(size_t)NODES_MAX * 64];     // scattered g sums
__device__ __align__(16) float g_degf[NODES_MAX];               // edge counts
__device__ int g_idx64;

__device__ __forceinline__ float gelu_exact(float v) {
    return 0.5f * v * (1.0f + erff(v * 0.70710678118654752440f));
}

__device__ __forceinline__ void fma2(ull_t& d, ull_t a, ull_t b) {
    asm("fma.rn.f32x2 %0, %1, %2, %0;" : "+l"(d) : "l"(a), "l"(b));
}
#define UNPK(lo, hi, v) asm("mov.b64 {%0,%1}, %2;" : "=f"(lo), "=f"(hi) : "l"(v))

// duplicated-weight-pair permutation: channel c -> 8B slot
// thread tx reads its 4 channels as two 16B loads at tx*16 and 256+tx*16
__device__ __forceinline__ int wperm(int c) {
    return ((c >> 1) & 1) * 32 + (c >> 2) * 2 + (c & 1);
}

// ---------------------------------------------------------------------------
__global__ void zero_scratch_kernel(int nG4, int nD4) {
    int idx = blockIdx.x * blockDim.x + threadIdx.x;
    if (idx < nG4)            ((float4*)g_G)[idx]          = make_float4(0.f, 0.f, 0.f, 0.f);
    else if (idx < nG4 + nD4) ((float4*)g_degf)[idx - nG4] = make_float4(0.f, 0.f, 0.f, 0.f);
}

__global__ void detect_idx_kernel(const void* edge_index, int N) {
    const long long* p64 = (const long long*)edge_index;
    int ok64 = 1;
    for (int e = 0; e < 128; ++e) {
        long long v = p64[e];
        if (v < 0 || v >= (long long)N) { ok64 = 0; break; }
    }
    g_idx64 = ok64;
}

__device__ __forceinline__ int load_edge_idx(const void* ei, long long pos, int idx64) {
    if (idx64) return (int)((const long long*)ei)[pos];
    return ((const int*)ei)[pos];
}

// ---------------------------------------------------------------------------
#define FMA_ROW(ACC, A, B)                          \
    ACC.x = fmaf((A), (B).x, ACC.x);                \
    ACC.y = fmaf((A), (B).y, ACC.y);                \
    ACC.z = fmaf((A), (B).z, ACC.z);                \
    ACC.w = fmaf((A), (B).w, ACC.w);

// Precompute g_AB. 64 nodes x 128 ch per CTA.
// xT stride 65 (conflict-free transposed stores, broadcast scalar reads).
// dyn smem: xT[64][65] (16.25KB, rounded) + Wc[64][128] (32KB)
__global__ void __launch_bounds__(NTHREADS, 2)
precompute_kernel(const float* __restrict__ x,
                  const float* __restrict__ W1,
                  const float* __restrict__ b1,
                  int N) {
    extern __shared__ float sm[];
    float* xT = sm;                  // [k][node], stride 65
    float* Wc = sm + 64 * 65 + 4;    // [k][c] 64x128 (offset keeps 16B align)

    int t = threadIdx.x;
    int n_base = blockIdx.x * 64;

#pragma unroll
    for (int it = 0; it < 32; ++it) {
        int idx = t + it * NTHREADS;
        int k = idx >> 7, c = idx & 127;
        Wc[idx] = (c < 64) ? W1[k * 64 + c] : W1[(64 + k) * 64 + (c - 64)];
    }
#pragma unroll
    for (int it = 0; it < 16; ++it) {
        int idx = t + it * NTHREADS;
        int node = idx >> 6, k = idx & 63;
        int gn = n_base + node;
        xT[k * 65 + node] = (gn < N) ? x[(size_t)gn * 64 + k] : 0.f;
    }
    __syncthreads();

    int tx = t & 31, ty = t >> 5;
    int c0 = tx * 4, n0 = ty * 8;

    float4 acc[8];
#pragma unroll
    for (int r = 0; r < 8; ++r) acc[r] = make_float4(0.f, 0.f, 0.f, 0.f);

#pragma unroll 8
    for (int k = 0; k < 64; ++k) {
        float4 b = *(const float4*)&Wc[k * 128 + c0];
        const float* xp = &xT[k * 65 + n0];
#pragma unroll
        for (int r = 0; r < 8; ++r) { FMA_ROW(acc[r], xp[r], b); }
    }

    float4 badd = make_float4(0.f, 0.f, 0.f, 0.f);
    if (c0 < 64) badd = *(const float4*)&b1[c0];

#pragma unroll
    for (int r = 0; r < 8; ++r) {
        int gn = n_base + n0 + r;
        if (gn < N) {
            float4 v = acc[r];
            v.x += badd.x; v.y += badd.y; v.z += badd.z; v.w += badd.w;
            *(float4*)&g_AB[(size_t)gn * 128 + c0] = v;
        }
    }
}

// ---------------------------------------------------------------------------
// Edge kernel. 128 edges/block, 256 threads, 4ch x 8edge per thread.
// dyn smem (bytes):
//   iidx[128] @0, jidx[128] @512
//   W1d [32][64] ull @1024   (16384)   permuted duplicated pairs
//   eaT [32][132] f32 @17408 (16896)
//   total 34304
__global__ void __launch_bounds__(NTHREADS, 2)
edge_kernel(const void* __restrict__ edge_index,
            const float* __restrict__ edge_attr,
            const float* __restrict__ W1,
            const float* __restrict__ gamma,
            const float* __restrict__ beta,
            int E) {
    extern __shared__ char smraw[];
    int*   iidx = (int*)smraw;
    int*   jidx = iidx + 128;
    ull_t* W1d  = (ull_t*)(smraw + 1024);
    float* eaT  = (float*)(smraw + 17408);

    int t = threadIdx.x;
    long long e_base = (long long)blockIdx.x * E_TILE;
    int idx64 = g_idx64;

    if (t < 128) iidx[t] = load_edge_idx(edge_index, e_base + t, idx64);
    else         jidx[t - 128] = load_edge_idx(edge_index, (long long)E + e_base + (t - 128), idx64);

    // duplicated + permuted W1 rows 128..159 (2048 pairs)
#pragma unroll
    for (int it = 0; it < 8; ++it) {
        int slot = t + it * NTHREADS;               // 0..2047
        int k = slot >> 6, c = slot & 63;
        float v = W1[128 * 64 + slot];
        ((float2*)W1d)[k * 64 + wperm(c)] = make_float2(v, v);
    }

    // edge_attr transposed: eaT[k][e]
    {
        const float4* ea4 = (const float4*)edge_attr;
#pragma unroll
        for (int it = 0; it < 4; ++it) {
            int slot = t + it * NTHREADS;           // 0..1023
            int e = slot >> 3, q = slot & 7;
            float4 v = ea4[e_base * 8 + slot];
            int k = q * 4;
            eaT[(k + 0) * 132 + e] = v.x;
            eaT[(k + 1) * 132 + e] = v.y;
            eaT[(k + 2) * 132 + e] = v.z;
            eaT[(k + 3) * 132 + e] = v.w;
        }
    }
    __syncthreads();

    int tx = t & 15, ty = t >> 4;
    int c0 = tx * 4, e0 = ty * 8;

    // acc[c*4+p]: channel c (0..3), edge-pair p (0..3)
    ull_t acc[16];
#pragma unroll
    for (int i = 0; i < 16; ++i) acc[i] = 0ull;

    // -------- GEMM1: h = ea @ W1c (fma.rn.f32x2, edge pairs in lanes) ------
#pragma unroll 4
    for (int kk = 0; kk < 32; ++kk) {
        const ull_t* wp = W1d + kk * 64 + tx * 2;
        ulonglong2 b0 = *(const ulonglong2*)(wp);        // ch c0, c0+1
        ulonglong2 b1 = *(const ulonglong2*)(wp + 32);   // ch c0+2, c0+3
        const float* ap = eaT + kk * 132 + e0;
        ulonglong2 A01 = *(const ulonglong2*)(ap);
        ulonglong2 A23 = *(const ulonglong2*)(ap + 4);
        fma2(acc[ 0], A01.x, b0.x); fma2(acc[ 1], A01.y, b0.x);
        fma2(acc[ 2], A23.x, b0.x); fma2(acc[ 3], A23.y, b0.x);
        fma2(acc[ 4], A01.x, b0.y); fma2(acc[ 5], A01.y, b0.y);
        fma2(acc[ 6], A23.x, b0.y); fma2(acc[ 7], A23.y, b0.y);
        fma2(acc[ 8], A01.x, b1.x); fma2(acc[ 9], A01.y, b1.x);
        fma2(acc[10], A23.x, b1.x); fma2(acc[11], A23.y, b1.x);
        fma2(acc[12], A01.x, b1.y); fma2(acc[13], A01.y, b1.y);
        fma2(acc[14], A23.x, b1.y); fma2(acc[15], A23.y, b1.y);
    }

    float hv[4][8];
#pragma unroll
    for (int c = 0; c < 4; ++c) {
#pragma unroll
        for (int p = 0; p < 4; ++p)
            UNPK(hv[c][2 * p], hv[c][2 * p + 1], acc[c * 4 + p]);
    }

    // -------- gather precomputed node parts --------
    const float4* AB4 = (const float4*)g_AB;
#pragma unroll
    for (int r = 0; r < 8; ++r) {
        int e = e0 + r;
        int vi = iidx[e], vj = jidx[e];
        float4 av = AB4[(size_t)vi * 32 + tx];        // A part
        float4 bv = AB4[(size_t)vj * 32 + 16 + tx];   // B part
        hv[0][r] += av.x + bv.x;
        hv[1][r] += av.y + bv.y;
        hv[2][r] += av.z + bv.z;
        hv[3][r] += av.w + bv.w;
    }

    // -------- LayerNorm + GELU --------
    float4 gmv = *(const float4*)&gamma[c0];
    float4 btv = *(const float4*)&beta[c0];
    float gm[4] = {gmv.x, gmv.y, gmv.z, gmv.w};
    float bt[4] = {btv.x, btv.y, btv.z, btv.w};

#pragma unroll
    for (int r = 0; r < 8; ++r) {
        float s = 0.f, s2 = 0.f;
#pragma unroll
        for (int c = 0; c < 4; ++c) {
            s += hv[c][r];
            s2 = fmaf(hv[c][r], hv[c][r], s2);
        }
#pragma unroll
        for (int off = 8; off >= 1; off >>= 1) {
            s  += __shfl_xor_sync(0xffffffffu, s,  off, 16);
            s2 += __shfl_xor_sync(0xffffffffu, s2, off, 16);
        }
        float mu   = s * (1.0f / 64.0f);
        float var  = s2 * (1.0f / 64.0f) - mu * mu;
        float rstd = rsqrtf(var + 1e-5f);
#pragma unroll
        for (int c = 0; c < 4; ++c)
            hv[c][r] = gelu_exact((hv[c][r] - mu) * rstd * gm[c] + bt[c]);
    }

    // -------- scatter g onto G[j], count degree --------
#pragma unroll
    for (int r = 0; r < 8; ++r) {
        int e = e0 + r;
        int vj = jidx[e];
        float* p = g_G + (size_t)vj * 64 + c0;
        asm volatile("red.global.add.v4.f32 [%0], {%1,%2,%3,%4};"
                     :: "l"(p), "f"(hv[0][r]), "f"(hv[1][r]),
                        "f"(hv[2][r]), "f"(hv[3][r]) : "memory");
        if (tx == 0) {
            float* dp = g_degf + vj;
            asm volatile("red.global.add.f32 [%0], %1;"
                         :: "l"(dp), "f"(1.0f) : "memory");
        }
    }
}

// ---------------------------------------------------------------------------
// Node kernel: out[n] = G[n] @ W2 + deg[n] * b2. 64 nodes per CTA.
// dyn smem: GT[64][65] (stride 65, conflict-free) + W2s[64][64]
__global__ void __launch_bounds__(NTHREADS, 2)
node_kernel(const float* __restrict__ W2,
            const float* __restrict__ b2,
            float* __restrict__ out,
            int N) {
    extern __shared__ float sm[];
    float* GT  = sm;                  // [k][node], stride 65
    float* W2s = sm + 64 * 65 + 4;    // [k][c] 64x64

    int t = threadIdx.x;
    int n_base = blockIdx.x * 64;

#pragma unroll
    for (int it = 0; it < 16; ++it) {
        int idx = t + it * NTHREADS;          // 0..4095
        int node = idx >> 6, k = idx & 63;
        int gn = n_base + node;
        GT[k * 65 + node] = (gn < N) ? g_G[(size_t)gn * 64 + k] : 0.f;
        W2s[idx] = W2[idx];
    }
    __syncthreads();

    int tx = t & 15, ty = t >> 4;
    int c0 = tx * 4, n0 = ty * 4;

    float4 acc[4];
#pragma unroll
    for (int r = 0; r < 4; ++r) acc[r] = make_float4(0.f, 0.f, 0.f, 0.f);

#pragma unroll 8
    for (int k = 0; k < 64; ++k) {
        float4 b = *(const float4*)&W2s[k * 64 + c0];
        const float* gp = &GT[k * 65 + n0];
#pragma unroll
        for (int r = 0; r < 4; ++r) { FMA_ROW(acc[r], gp[r], b); }
    }

    float4 b2v = *(const float4*)&b2[c0];
#pragma unroll
    for (int r = 0; r < 4; ++r) {
        int gn = n_base + n0 + r;
        if (gn < N) {
            float d = g_degf[gn];
            float4 v = acc[r];
            v.x = fmaf(d, b2v.x, v.x); v.y = fmaf(d, b2v.y, v.y);
            v.z = fmaf(d, b2v.z, v.z); v.w = fmaf(d, b2v.w, v.w);
            *(float4*)&out[(size_t)gn * 64 + c0] = v;
        }
    }
}

// ---------------------------------------------------------------------------
extern "C" void kernel_launch(void* const* d_in, const int* in_sizes, int n_in,
                              void* d_out, int out_size) {
    const float* x          = (const float*)d_in[0];
    const void*  edge_index = d_in[1];
    const float* edge_attr  = (const float*)d_in[2];
    const float* W1         = (const float*)d_in[3];
    const float* b1         = (const float*)d_in[4];
    const float* gamma      = (const float*)d_in[5];
    const float* beta       = (const float*)d_in[6];
    const float* W2         = (const float*)d_in[7];
    const float* b2         = (const float*)d_in[8];
    float*       out        = (float*)d_out;

    int N = in_sizes[0] / 64;     // 100000
    int E = in_sizes[2] / 32;     // 1600000

    const int SM_PRE  = (64 * 65 + 4 + 64 * 128) * 4;   // ~49.4 KB
    const int SM_EDGE = 34304;
    const int SM_NODE = (64 * 65 + 4 + 64 * 64) * 4;    // ~33 KB
    cudaFuncSetAttribute(precompute_kernel, cudaFuncAttributeMaxDynamicSharedMemorySize, SM_PRE);
    cudaFuncSetAttribute(edge_kernel,       cudaFuncAttributeMaxDynamicSharedMemorySize, SM_EDGE);
    cudaFuncSetAttribute(node_kernel,       cudaFuncAttributeMaxDynamicSharedMemorySize, SM_NODE);

    int nG4 = N * 16;                       // G float4 count
    int nD4 = (N + 3) / 4;                  // deg float4 count
    int nz  = nG4 + nD4;

    detect_idx_kernel<<<1, 1>>>(edge_index, N);
    zero_scratch_kernel<<<(nz + 255) / 256, 256>>>(nG4, nD4);
    precompute_kernel<<<(N + 63) / 64, NTHREADS, SM_PRE>>>(x, W1, b1, N);
    edge_kernel<<<E / E_TILE, NTHREADS, SM_EDGE>>>(edge_index, edge_attr, W1,
                                                   gamma, beta, E);
    node_kernel<<<(N + 63) / 64, NTHREADS, SM_NODE>>>(W2, b2, out, N);
}

// round 6
// speedup vs baseline: 3.9812x; 1.0759x over previous
#include <cuda_runtime.h>
#include <cstdint>
#include <cstddef>

// ---------------------------------------------------------------------------
// MPConv fused GNN edge-MLP + scatter on GB300 (sm_103a)
// R6 = R5 (hoisted GEMM2) + 3 CTAs/SM edge kernel via pair-by-pair epilogue
//      (register diet: peak live state ~50 scalars instead of ~80).
// ---------------------------------------------------------------------------

#define NODES_MAX 100000
#define E_TILE    128
#define NTHREADS  256

typedef unsigned long long ull_t;

__device__ __align__(16) float g_AB[(size_t)NODES_MAX * 128];   // A||B per node
__device__ __align__(16) float g_G[(size_t)NODES_MAX * 64];     // scattered g sums
__device__ __align__(16) float g_degf[NODES_MAX];               // edge counts
__device__ int g_idx64;

__device__ __forceinline__ float gelu_exact(float v) {
    return 0.5f * v * (1.0f + erff(v * 0.70710678118654752440f));
}

__device__ __forceinline__ void fma2(ull_t& d, ull_t a, ull_t b) {
    asm("fma.rn.f32x2 %0, %1, %2, %0;" : "+l"(d) : "l"(a), "l"(b));
}
#define UNPK(lo, hi, v) asm("mov.b64 {%0,%1}, %2;" : "=f"(lo), "=f"(hi) : "l"(v))

// duplicated-weight-pair permutation: channel c -> 8B slot; thread tx reads its
// 4 channels as two 16B loads at tx*16 and 256+tx*16 (conflict-free).
__device__ __forceinline__ int wperm(int c) {
    return ((c >> 1) & 1) * 32 + (c >> 2) * 2 + (c & 1);
}

// ---------------------------------------------------------------------------
__global__ void zero_scratch_kernel(int nG4, int nD4) {
    int idx = blockIdx.x * blockDim.x + threadIdx.x;
    if (idx < nG4)            ((float4*)g_G)[idx]          = make_float4(0.f, 0.f, 0.f, 0.f);
    else if (idx < nG4 + nD4) ((float4*)g_degf)[idx - nG4] = make_float4(0.f, 0.f, 0.f, 0.f);
}

__global__ void detect_idx_kernel(const void* edge_index, int N) {
    const long long* p64 = (const long long*)edge_index;
    int ok64 = 1;
    for (int e = 0; e < 128; ++e) {
        long long v = p64[e];
        if (v < 0 || v >= (long long)N) { ok64 = 0; break; }
    }
    g_idx64 = ok64;
}

__device__ __forceinline__ int load_edge_idx(const void* ei, long long pos, int idx64) {
    if (idx64) return (int)((const long long*)ei)[pos];
    return ((const int*)ei)[pos];
}

// ---------------------------------------------------------------------------
#define FMA_ROW(ACC, A, B)                          \
    ACC.x = fmaf((A), (B).x, ACC.x);                \
    ACC.y = fmaf((A), (B).y, ACC.y);                \
    ACC.z = fmaf((A), (B).z, ACC.z);                \
    ACC.w = fmaf((A), (B).w, ACC.w);

// Precompute g_AB. 64 nodes x 128 ch per CTA, xT stride 65 (conflict-free).
__global__ void __launch_bounds__(NTHREADS, 2)
precompute_kernel(const float* __restrict__ x,
                  const float* __restrict__ W1,
                  const float* __restrict__ b1,
                  int N) {
    extern __shared__ float sm[];
    float* xT = sm;                  // [k][node], stride 65
    float* Wc = sm + 64 * 65 + 4;    // [k][c] 64x128

    int t = threadIdx.x;
    int n_base = blockIdx.x * 64;

#pragma unroll
    for (int it = 0; it < 32; ++it) {
        int idx = t + it * NTHREADS;
        int k = idx >> 7, c = idx & 127;
        Wc[idx] = (c < 64) ? W1[k * 64 + c] : W1[(64 + k) * 64 + (c - 64)];
    }
#pragma unroll
    for (int it = 0; it < 16; ++it) {
        int idx = t + it * NTHREADS;
        int node = idx >> 6, k = idx & 63;
        int gn = n_base + node;
        xT[k * 65 + node] = (gn < N) ? x[(size_t)gn * 64 + k] : 0.f;
    }
    __syncthreads();

    int tx = t & 31, ty = t >> 5;
    int c0 = tx * 4, n0 = ty * 8;

    float4 acc[8];
#pragma unroll
    for (int r = 0; r < 8; ++r) acc[r] = make_float4(0.f, 0.f, 0.f, 0.f);

#pragma unroll 8
    for (int k = 0; k < 64; ++k) {
        float4 b = *(const float4*)&Wc[k * 128 + c0];
        const float* xp = &xT[k * 65 + n0];
#pragma unroll
        for (int r = 0; r < 8; ++r) { FMA_ROW(acc[r], xp[r], b); }
    }

    float4 badd = make_float4(0.f, 0.f, 0.f, 0.f);
    if (c0 < 64) badd = *(const float4*)&b1[c0];

#pragma unroll
    for (int r = 0; r < 8; ++r) {
        int gn = n_base + n0 + r;
        if (gn < N) {
            float4 v = acc[r];
            v.x += badd.x; v.y += badd.y; v.z += badd.z; v.w += badd.w;
            *(float4*)&g_AB[(size_t)gn * 128 + c0] = v;
        }
    }
}

// ---------------------------------------------------------------------------
// Edge kernel. 128 edges/block, 256 threads, 4ch x 8edge per thread.
// dyn smem (34304 B): iidx@0, jidx@512, W1d[32][64]ull@1024, eaT[32][132]@17408
__global__ void __launch_bounds__(NTHREADS, 3)
edge_kernel(const void* __restrict__ edge_index,
            const float* __restrict__ edge_attr,
            const float* __restrict__ W1,
            const float* __restrict__ gamma,
            const float* __restrict__ beta,
            int E) {
    extern __shared__ char smraw[];
    int*   iidx = (int*)smraw;
    int*   jidx = iidx + 128;
    ull_t* W1d  = (ull_t*)(smraw + 1024);
    float* eaT  = (float*)(smraw + 17408);

    int t = threadIdx.x;
    long long e_base = (long long)blockIdx.x * E_TILE;
    int idx64 = g_idx64;

    if (t < 128) iidx[t] = load_edge_idx(edge_index, e_base + t, idx64);
    else         jidx[t - 128] = load_edge_idx(edge_index, (long long)E + e_base + (t - 128), idx64);

    // duplicated + permuted W1 rows 128..159 (2048 pairs)
#pragma unroll
    for (int it = 0; it < 8; ++it) {
        int slot = t + it * NTHREADS;               // 0..2047
        int k = slot >> 6, c = slot & 63;
        float v = W1[128 * 64 + slot];
        ((float2*)W1d)[k * 64 + wperm(c)] = make_float2(v, v);
    }

    // edge_attr transposed: eaT[k][e]
    {
        const float4* ea4 = (const float4*)edge_attr;
#pragma unroll
        for (int it = 0; it < 4; ++it) {
            int slot = t + it * NTHREADS;           // 0..1023
            int e = slot >> 3, q = slot & 7;
            float4 v = ea4[e_base * 8 + slot];
            int k = q * 4;
            eaT[(k + 0) * 132 + e] = v.x;
            eaT[(k + 1) * 132 + e] = v.y;
            eaT[(k + 2) * 132 + e] = v.z;
            eaT[(k + 3) * 132 + e] = v.w;
        }
    }
    __syncthreads();

    int tx = t & 15, ty = t >> 4;
    int c0 = tx * 4, e0 = ty * 8;

    // acc[c*4+p]: channel c (0..3), edge-pair p (0..3), lanes = (e0+2p, e0+2p+1)
    ull_t acc[16];
#pragma unroll
    for (int i = 0; i < 16; ++i) acc[i] = 0ull;

    // -------- GEMM1: h = ea @ W1c (fma.rn.f32x2) --------
#pragma unroll 4
    for (int kk = 0; kk < 32; ++kk) {
        const ull_t* wp = W1d + kk * 64 + tx * 2;
        ulonglong2 b0 = *(const ulonglong2*)(wp);        // ch c0, c0+1
        ulonglong2 b1 = *(const ulonglong2*)(wp + 32);   // ch c0+2, c0+3
        const float* ap = eaT + kk * 132 + e0;
        ulonglong2 A01 = *(const ulonglong2*)(ap);
        ulonglong2 A23 = *(const ulonglong2*)(ap + 4);
        fma2(acc[ 0], A01.x, b0.x); fma2(acc[ 1], A01.y, b0.x);
        fma2(acc[ 2], A23.x, b0.x); fma2(acc[ 3], A23.y, b0.x);
        fma2(acc[ 4], A01.x, b0.y); fma2(acc[ 5], A01.y, b0.y);
        fma2(acc[ 6], A23.x, b0.y); fma2(acc[ 7], A23.y, b0.y);
        fma2(acc[ 8], A01.x, b1.x); fma2(acc[ 9], A01.y, b1.x);
        fma2(acc[10], A23.x, b1.x); fma2(acc[11], A23.y, b1.x);
        fma2(acc[12], A01.x, b1.y); fma2(acc[13], A01.y, b1.y);
        fma2(acc[14], A23.x, b1.y); fma2(acc[15], A23.y, b1.y);
    }

    // -------- epilogue, pair-by-pair (register diet) --------
    float4 gmv = *(const float4*)&gamma[c0];
    float4 btv = *(const float4*)&beta[c0];
    const float4* AB4 = (const float4*)g_AB;

#pragma unroll
    for (int p = 0; p < 4; ++p) {
        int ea = e0 + 2 * p, eb = ea + 1;

        // unpack this pair's 4 channels: va = edge ea, vb = edge eb
        float va0, vb0, va1, vb1, va2, vb2, va3, vb3;
        UNPK(va0, vb0, acc[0 * 4 + p]);
        UNPK(va1, vb1, acc[1 * 4 + p]);
        UNPK(va2, vb2, acc[2 * 4 + p]);
        UNPK(va3, vb3, acc[3 * 4 + p]);

        // gather node parts for both edges
        {
            float4 Aa = AB4[(size_t)iidx[ea] * 32 + tx];
            float4 Ba = AB4[(size_t)jidx[ea] * 32 + 16 + tx];
            va0 += Aa.x + Ba.x; va1 += Aa.y + Ba.y;
            va2 += Aa.z + Ba.z; va3 += Aa.w + Ba.w;
        }
        {
            float4 Ab = AB4[(size_t)iidx[eb] * 32 + tx];
            float4 Bb = AB4[(size_t)jidx[eb] * 32 + 16 + tx];
            vb0 += Ab.x + Bb.x; vb1 += Ab.y + Bb.y;
            vb2 += Ab.z + Bb.z; vb3 += Ab.w + Bb.w;
        }

        // LayerNorm sums for both edges (reduce across 16 tx lanes)
        float sa = va0 + va1 + va2 + va3;
        float sb = vb0 + vb1 + vb2 + vb3;
        float qa = fmaf(va0, va0, fmaf(va1, va1, fmaf(va2, va2, va3 * va3)));
        float qb = fmaf(vb0, vb0, fmaf(vb1, vb1, fmaf(vb2, vb2, vb3 * vb3)));
#pragma unroll
        for (int off = 8; off >= 1; off >>= 1) {
            sa += __shfl_xor_sync(0xffffffffu, sa, off, 16);
            sb += __shfl_xor_sync(0xffffffffu, sb, off, 16);
            qa += __shfl_xor_sync(0xffffffffu, qa, off, 16);
            qb += __shfl_xor_sync(0xffffffffu, qb, off, 16);
        }
        float mua = sa * (1.0f / 64.0f);
        float mub = sb * (1.0f / 64.0f);
        float ra  = rsqrtf(qa * (1.0f / 64.0f) - mua * mua + 1e-5f);
        float rb  = rsqrtf(qb * (1.0f / 64.0f) - mub * mub + 1e-5f);

        va0 = gelu_exact((va0 - mua) * ra * gmv.x + btv.x);
        va1 = gelu_exact((va1 - mua) * ra * gmv.y + btv.y);
        va2 = gelu_exact((va2 - mua) * ra * gmv.z + btv.z);
        va3 = gelu_exact((va3 - mua) * ra * gmv.w + btv.w);
        vb0 = gelu_exact((vb0 - mub) * rb * gmv.x + btv.x);
        vb1 = gelu_exact((vb1 - mub) * rb * gmv.y + btv.y);
        vb2 = gelu_exact((vb2 - mub) * rb * gmv.z + btv.z);
        vb3 = gelu_exact((vb3 - mub) * rb * gmv.w + btv.w);

        // scatter g onto G[j] for both edges; degree from lane tx==0
        {
            int vja = jidx[ea];
            float* pa = g_G + (size_t)vja * 64 + c0;
            asm volatile("red.global.add.v4.f32 [%0], {%1,%2,%3,%4};"
                         :: "l"(pa), "f"(va0), "f"(va1), "f"(va2), "f"(va3) : "memory");
            int vjb = jidx[eb];
            float* pb = g_G + (size_t)vjb * 64 + c0;
            asm volatile("red.global.add.v4.f32 [%0], {%1,%2,%3,%4};"
                         :: "l"(pb), "f"(vb0), "f"(vb1), "f"(vb2), "f"(vb3) : "memory");
            if (tx == 0) {
                asm volatile("red.global.add.f32 [%0], %1;"
                             :: "l"(g_degf + vja), "f"(1.0f) : "memory");
                asm volatile("red.global.add.f32 [%0], %1;"
                             :: "l"(g_degf + vjb), "f"(1.0f) : "memory");
            }
        }
    }
}

// ---------------------------------------------------------------------------
// Node kernel: out[n] = G[n] @ W2 + deg[n] * b2. 64 nodes per CTA.
__global__ void __launch_bounds__(NTHREADS, 2)
node_kernel(const float* __restrict__ W2,
            const float* __restrict__ b2,
            float* __restrict__ out,
            int N) {
    extern __shared__ float sm[];
    float* GT  = sm;                  // [k][node], stride 65
    float* W2s = sm + 64 * 65 + 4;    // [k][c] 64x64

    int t = threadIdx.x;
    int n_base = blockIdx.x * 64;

#pragma unroll
    for (int it = 0; it < 16; ++it) {
        int idx = t + it * NTHREADS;
        int node = idx >> 6, k = idx & 63;
        int gn = n_base + node;
        GT[k * 65 + node] = (gn < N) ? g_G[(size_t)gn * 64 + k] : 0.f;
        W2s[idx] = W2[idx];
    }
    __syncthreads();

    int tx = t & 15, ty = t >> 4;
    int c0 = tx * 4, n0 = ty * 4;

    float4 acc[4];
#pragma unroll
    for (int r = 0; r < 4; ++r) acc[r] = make_float4(0.f, 0.f, 0.f, 0.f);

#pragma unroll 8
    for (int k = 0; k < 64; ++k) {
        float4 b = *(const float4*)&W2s[k * 64 + c0];
        const float* gp = &GT[k * 65 + n0];
#pragma unroll
        for (int r = 0; r < 4; ++r) { FMA_ROW(acc[r], gp[r], b); }
    }

    float4 b2v = *(const float4*)&b2[c0];
#pragma unroll
    for (int r = 0; r < 4; ++r) {
        int gn = n_base + n0 + r;
        if (gn < N) {
            float d = g_degf[gn];
            float4 v = acc[r];
            v.x = fmaf(d, b2v.x, v.x); v.y = fmaf(d, b2v.y, v.y);
            v.z = fmaf(d, b2v.z, v.z); v.w = fmaf(d, b2v.w, v.w);
            *(float4*)&out[(size_t)gn * 64 + c0] = v;
        }
    }
}

// ---------------------------------------------------------------------------
extern "C" void kernel_launch(void* const* d_in, const int* in_sizes, int n_in,
                              void* d_out, int out_size) {
    const float* x          = (const float*)d_in[0];
    const void*  edge_index = d_in[1];
    const float* edge_attr  = (const float*)d_in[2];
    const float* W1         = (const float*)d_in[3];
    const float* b1         = (const float*)d_in[4];
    const float* gamma      = (const float*)d_in[5];
    const float* beta       = (const float*)d_in[6];
    const float* W2         = (const float*)d_in[7];
    const float* b2         = (const float*)d_in[8];
    float*       out        = (float*)d_out;

    int N = in_sizes[0] / 64;     // 100000
    int E = in_sizes[2] / 32;     // 1600000

    const int SM_PRE  = (64 * 65 + 4 + 64 * 128) * 4;
    const int SM_EDGE = 34304;
    const int SM_NODE = (64 * 65 + 4 + 64 * 64) * 4;
    cudaFuncSetAttribute(precompute_kernel, cudaFuncAttributeMaxDynamicSharedMemorySize, SM_PRE);
    cudaFuncSetAttribute(edge_kernel,       cudaFuncAttributeMaxDynamicSharedMemorySize, SM_EDGE);
    cudaFuncSetAttribute(node_kernel,       cudaFuncAttributeMaxDynamicSharedMemorySize, SM_NODE);

    int nG4 = N * 16;
    int nD4 = (N + 3) / 4;
    int nz  = nG4 + nD4;

    detect_idx_kernel<<<1, 1>>>(edge_index, N);
    zero_scratch_kernel<<<(nz + 255) / 256, 256>>>(nG4, nD4);
    precompute_kernel<<<(N + 63) / 64, NTHREADS, SM_PRE>>>(x, W1, b1, N);
    edge_kernel<<<E / E_TILE, NTHREADS, SM_EDGE>>>(edge_index, edge_attr, W1,
                                                   gamma, beta, E);
    node_kernel<<<(N + 63) / 64, NTHREADS, SM_NODE>>>(W2, b2, out, N);
}